// round 1
// baseline (speedup 1.0000x reference)
#include <cuda_runtime.h>
#include <cstdint>

#define THREADS   512
#define BE        32          // edges per CTA
#define DEMB      256
#define NG        50
#define K_IN      306         // DEMB + NG
#define HID       512
#define HEADS     8
#define NELEM     100
#define KT1       34          // 306 = 9 * 34
#define NT1       9
#define KT2       25          // 50 = 2 * 25
#define NT2       2
#define NTILES    (NT1 + NT2)
#define XSTRIDE   36          // padded edge stride (floats): conflict-free + 16B aligned

// ---- shared memory layout (float offsets) ----
#define XS_OFF    0                         // 306*36 = 11016
#define WS0_OFF   11016                     // 34*512 = 17408
#define WS1_OFF   (WS0_OFF + 17408)         // 28424
#define WOS_OFF   (WS1_OFF + 17408)         // 45832, 512*8 = 4096
#define BS_OFF    (WOS_OFF + 4096)          // 49928, 512
#define BO_OFF    (BS_OFF + 512)            // 50440, 8
#define PIDX_OFF  (BO_OFF + 8)              // 50448, 32 (ints)
#define DL_OFF    (PIDX_OFF + 32)           // 50480, 32
#define SMEM_FLOATS (DL_OFF + 32)           // 50512
#define SMEM_BYTES  (SMEM_FLOATS * 4)       // 202048 B

// W_in^T and gate_W^T concatenated: rows 0..305 = W_in^T, rows 306..355 = gate_W^T
__device__ float g_Wc[(K_IN + NG) * HID];

typedef unsigned long long ull;

__device__ __forceinline__ void fma2(ull& d, ull a, ull b) {
    asm("fma.rn.f32x2 %0, %1, %2, %0;" : "+l"(d) : "l"(a), "l"(b));
}
__device__ __forceinline__ ull pack2(float x, float y) {
    ull r; asm("mov.b64 %0, {%1, %2};" : "=l"(r) : "f"(x), "f"(y)); return r;
}
__device__ __forceinline__ float2 unpack2(ull v) {
    float2 r; asm("mov.b64 {%0, %1}, %2;" : "=f"(r.x), "=f"(r.y) : "l"(v)); return r;
}
__device__ __forceinline__ void cp16(uint32_t sa, const void* g) {
    asm volatile("cp.async.cg.shared.global [%0], [%1], 16;" :: "r"(sa), "l"(g));
}
__device__ __forceinline__ void cp_commit() { asm volatile("cp.async.commit_group;"); }
__device__ __forceinline__ void cp_wait1()  { asm volatile("cp.async.wait_group 1;"); }

// -------- weight transpose: g_Wc[k][j] = W_in[j][k] (k<306) / gate_W[j][k-306] --------
__global__ void transpose_w_kernel(const float* __restrict__ W_in,
                                   const float* __restrict__ gate_W) {
    int idx = blockIdx.x * blockDim.x + threadIdx.x;
    if (idx >= (K_IN + NG) * HID) return;
    int k = idx >> 9;          // / 512
    int j = idx & (HID - 1);
    float v = (k < K_IN) ? W_in[j * K_IN + k] : gate_W[j * NG + (k - K_IN)];
    g_Wc[idx] = v;
}

// 16 packed f32x2 FMAs: acc[e][jp] += W[kk][jbase + 2jp .. +1] * x[e]
__device__ __forceinline__ void fma_block(ull (&acc)[4][4], const float* xr, const float* wr) {
    float4 xv = *(const float4*)xr;        // 4 edges at this k
    float4 wa = *(const float4*)wr;        // hidden pair values
    float4 wb = *(const float4*)(wr + 4);
    ull w0 = pack2(wa.x, wa.y), w1 = pack2(wa.z, wa.w);
    ull w2 = pack2(wb.x, wb.y), w3 = pack2(wb.z, wb.w);
    ull x0 = pack2(xv.x, xv.x), x1 = pack2(xv.y, xv.y);
    ull x2 = pack2(xv.z, xv.z), x3 = pack2(xv.w, xv.w);
    fma2(acc[0][0], w0, x0); fma2(acc[0][1], w1, x0);
    fma2(acc[0][2], w2, x0); fma2(acc[0][3], w3, x0);
    fma2(acc[1][0], w0, x1); fma2(acc[1][1], w1, x1);
    fma2(acc[1][2], w2, x1); fma2(acc[1][3], w3, x1);
    fma2(acc[2][0], w0, x2); fma2(acc[2][1], w1, x2);
    fma2(acc[2][2], w2, x2); fma2(acc[2][3], w3, x2);
    fma2(acc[3][0], w0, x3); fma2(acc[3][1], w1, x3);
    fma2(acc[3][2], w2, x3); fma2(acc[3][3], w3, x3);
}

__global__ void __launch_bounds__(THREADS, 1)
pair_embed_main(const int* __restrict__ anum,
                const int* __restrict__ edge_index,
                const int* __restrict__ edge_to_src,
                const float* __restrict__ dist,
                const float* __restrict__ emb_table,
                const float* __restrict__ b_in,
                const float* __restrict__ W_out,
                const float* __restrict__ b_out,
                float* __restrict__ out, int E) {
    extern __shared__ float sm[];
    float* Xs   = sm + XS_OFF;
    float* WsA  = sm + WS0_OFF;
    float* WsB  = sm + WS1_OFF;
    float* Wos  = sm + WOS_OFF;
    float* bs   = sm + BS_OFF;
    float* bo   = sm + BO_OFF;
    int*   pidx = (int*)(sm + PIDX_OFF);
    float* dl   = sm + DL_OFF;

    const int tid   = threadIdx.x;
    const int e0    = blockIdx.x * BE;
    const int eg    = tid & 7;       // 8 edge-groups of 4 edges
    const int jg    = tid >> 3;      // 64 hidden-groups of 8 hiddens
    const int jbase = jg * 8;

    // ---- stage indices, dist, W_out (as [j][head]), biases ----
    if (tid < BE) {
        int e = e0 + tid;
        int f = (e < E) ? edge_to_src[e] : 0;
        int i0 = edge_index[f];
        int i1 = edge_index[E + f];
        pidx[tid] = anum[i0] + NELEM * anum[i1];
        dl[tid]   = (e < E) ? dist[e] : 0.0f;
    }
    for (int i = tid; i < HID * HEADS; i += THREADS)
        Wos[i] = W_out[(i & 7) * HID + (i >> 3)];
    for (int i = tid; i < HID; i += THREADS) bs[i] = b_in[i];
    if (tid < HEADS) bo[tid] = b_out[tid];
    __syncthreads();

    // ---- stage X = [emb(256) ; rbf(50)] transposed: Xs[k][e], stride 36 ----
    for (int i = tid; i < BE * (DEMB / 4); i += THREADS) {
        int e = i >> 6, c = i & 63;
        float4 v = ((const float4*)emb_table)[pidx[e] * (DEMB / 4) + c];
        int kb = c * 4;
        Xs[(kb + 0) * XSTRIDE + e] = v.x;
        Xs[(kb + 1) * XSTRIDE + e] = v.y;
        Xs[(kb + 2) * XSTRIDE + e] = v.z;
        Xs[(kb + 3) * XSTRIDE + e] = v.w;
    }
    {
        const float delta = 12.0f / 49.0f;
        const float coeff = -0.5f / (delta * delta);
        for (int i = tid; i < BE * NG; i += THREADS) {
            int e = i / NG, g = i - e * NG;
            float d = dl[e] - (float)g * delta;
            Xs[(DEMB + g) * XSTRIDE + e] = __expf(coeff * d * d);
        }
    }

    // ---- issue tile 0 (cp.async double-buffered weight stream) ----
    {
        uint32_t sbase = (uint32_t)__cvta_generic_to_shared(WsA);
        const float4* src = (const float4*)g_Wc;
        for (int i = tid; i < KT1 * 128; i += THREADS) cp16(sbase + i * 16, src + i);
    }
    cp_commit();

    ull accp[4][4], accg[4][4];
#pragma unroll
    for (int a = 0; a < 4; a++)
#pragma unroll
        for (int b = 0; b < 4; b++) { accp[a][b] = 0ull; accg[a][b] = 0ull; }

    for (int t = 0; t < NTILES; ++t) {
        if (t + 1 < NTILES) {
            int r0 = (t + 1 < NT1) ? (t + 1) * KT1 : K_IN + (t + 1 - NT1) * KT2;
            int nr = (t + 1 < NT1) ? KT1 : KT2;
            float* dstb = ((t + 1) & 1) ? WsB : WsA;
            uint32_t sbase = (uint32_t)__cvta_generic_to_shared(dstb);
            const float4* src = (const float4*)(g_Wc + r0 * HID);
            for (int i = tid; i < nr * 128; i += THREADS) cp16(sbase + i * 16, src + i);
        }
        cp_commit();
        cp_wait1();           // tile t resident (≤1 group pending = tile t+1)
        __syncthreads();

        const float* W = (t & 1) ? WsB : WsA;
        if (t < NT1) {
            const int kb = t * KT1;
#pragma unroll
            for (int kk = 0; kk < KT1; ++kk)
                fma_block(accp, Xs + (kb + kk) * XSTRIDE + eg * 4,
                          W + kk * HID + jbase);
        } else {
            const int gb = (t - NT1) * KT2;
#pragma unroll
            for (int kk = 0; kk < KT2; ++kk)
                fma_block(accg, Xs + (DEMB + gb + kk) * XSTRIDE + eg * 4,
                          W + kk * HID + jbase);
        }
        __syncthreads();      // protect alt buffer before next issue
    }

    // ---- epilogue: h = silu(pre + b) * gate ; partial head outputs ----
    float po[4][8];
#pragma unroll
    for (int e = 0; e < 4; e++)
#pragma unroll
        for (int h = 0; h < 8; h++) po[e][h] = 0.0f;

#pragma unroll
    for (int jp = 0; jp < 4; ++jp) {
        int j0 = jbase + jp * 2;
        float bx = bs[j0], by = bs[j0 + 1];
        float4 wA0 = *(const float4*)(Wos + j0 * 8);
        float4 wA1 = *(const float4*)(Wos + j0 * 8 + 4);
        float4 wB0 = *(const float4*)(Wos + (j0 + 1) * 8);
        float4 wB1 = *(const float4*)(Wos + (j0 + 1) * 8 + 4);
#pragma unroll
        for (int e = 0; e < 4; ++e) {
            float2 p = unpack2(accp[e][jp]);
            p.x += bx; p.y += by;
            float2 gt = unpack2(accg[e][jp]);
            float h0 = p.x * __fdividef(1.0f, 1.0f + __expf(-p.x)) * gt.x;
            float h1 = p.y * __fdividef(1.0f, 1.0f + __expf(-p.y)) * gt.y;
            po[e][0] += h0 * wA0.x + h1 * wB0.x;
            po[e][1] += h0 * wA0.y + h1 * wB0.y;
            po[e][2] += h0 * wA0.z + h1 * wB0.z;
            po[e][3] += h0 * wA0.w + h1 * wB0.w;
            po[e][4] += h0 * wA1.x + h1 * wB1.x;
            po[e][5] += h0 * wA1.y + h1 * wB1.y;
            po[e][6] += h0 * wA1.z + h1 * wB1.z;
            po[e][7] += h0 * wA1.w + h1 * wB1.w;
        }
    }

    // ---- deterministic cross-thread reduction over the 64 hidden-groups ----
    // Rbuf[jg][e][h] with per-e stride 9 -> conflict-free reads (9e+h mod 32 distinct)
    float* Rb = WsA;   // 18432 floats, overlays dead weight buffers
#pragma unroll
    for (int el = 0; el < 4; ++el)
#pragma unroll
        for (int h = 0; h < 8; ++h)
            Rb[jg * 288 + (eg * 4 + el) * 9 + h] = po[el][h];
    __syncthreads();

    if (tid < BE * HEADS) {
        int h = tid >> 5;          // warp per head
        int e = tid & 31;          // coalesced edges
        float s = bo[h];
#pragma unroll 8
        for (int q = 0; q < 64; ++q) s += Rb[q * 288 + e * 9 + h];
        int ge = e0 + e;
        if (ge < E) out[h * E + ge] = s;
    }
}

extern "C" void kernel_launch(void* const* d_in, const int* in_sizes, int n_in,
                              void* d_out, int out_size) {
    const int*   anum        = (const int*)d_in[0];
    const int*   edge_index  = (const int*)d_in[1];
    const int*   edge_to_src = (const int*)d_in[2];
    const float* dist        = (const float*)d_in[3];
    const float* emb_table   = (const float*)d_in[4];
    const float* gate_W      = (const float*)d_in[5];
    const float* W_in        = (const float*)d_in[6];
    const float* b_in        = (const float*)d_in[7];
    const float* W_out       = (const float*)d_in[8];
    const float* b_out       = (const float*)d_in[9];
    float* out = (float*)d_out;

    const int E = in_sizes[2];   // edge_to_src element count

    // 1) transpose weights into __device__ scratch (coalesced streaming later)
    {
        int tot = (K_IN + NG) * HID;
        transpose_w_kernel<<<(tot + 255) / 256, 256>>>(W_in, gate_W);
    }

    // 2) fused main kernel
    cudaFuncSetAttribute(pair_embed_main,
                         cudaFuncAttributeMaxDynamicSharedMemorySize, SMEM_BYTES);
    int grid = (E + BE - 1) / BE;
    pair_embed_main<<<grid, THREADS, SMEM_BYTES>>>(
        anum, edge_index, edge_to_src, dist, emb_table,
        b_in, W_out, b_out, out, E);
}

// round 3
// speedup vs baseline: 7.5759x; 7.5759x over previous
#include <cuda_runtime.h>
#include <cuda_bf16.h>
#include <cstdint>

#define NB        4096
#define HID       512
#define KEMB      256
#define NG        50
#define NELEM     100
#define NPAIR     (NELEM * NELEM)       // 10000
#define HEADS     8
#define RBF_R     12.0f

// ---------------- device scratch ----------------
__device__ __align__(16) float          g_P[(size_t)NPAIR * HID];     // emb@W^T + b_in
__device__ __align__(16) float          g_T1v[(size_t)(NB + 1) * HID];
__device__ __align__(16) float          g_T2v[(size_t)(NB + 1) * HID];
__device__ __align__(16) __nv_bfloat16  g_T1s[(size_t)NB * HID];
__device__ __align__(16) __nv_bfloat16  g_T2s[(size_t)NB * HID];
__device__ __align__(16) float          g_WT[KEMB * HID];             // W_in emb part, [k][j]
__device__ __align__(16) float          g_Wr[NG * HID];               // W_in rbf part, [g][j]
__device__ __align__(16) float          g_Wg[NG * HID];               // gate_W,       [g][j]

typedef unsigned long long ull;

__device__ __forceinline__ void fma2(ull& d, ull a, ull b) {
    asm("fma.rn.f32x2 %0, %1, %2, %0;" : "+l"(d) : "l"(a), "l"(b));
}
__device__ __forceinline__ ull pack2(float x, float y) {
    ull r; asm("mov.b64 %0, {%1, %2};" : "=l"(r) : "f"(x), "f"(y)); return r;
}
__device__ __forceinline__ float2 unpack2(ull v) {
    float2 r; asm("mov.b64 {%0, %1}, %2;" : "=f"(r.x), "=f"(r.y) : "l"(v)); return r;
}
__device__ __forceinline__ void cp16(uint32_t sa, const void* g) {
    asm volatile("cp.async.cg.shared.global [%0], [%1], 16;" :: "r"(sa), "l"(g));
}
__device__ __forceinline__ void cp_commit() { asm volatile("cp.async.commit_group;"); }
__device__ __forceinline__ void cp_wait1()  { asm volatile("cp.async.wait_group 1;"); }

// ================= prep 0: transposes =================
__global__ void prep_transpose(const float* __restrict__ W_in,
                               const float* __restrict__ gate_W) {
    int idx = blockIdx.x * blockDim.x + threadIdx.x;
    int total = KEMB * HID + NG * HID * 2;
    if (idx >= total) return;
    if (idx < KEMB * HID) {
        int k = idx >> 9, j = idx & (HID - 1);
        g_WT[idx] = W_in[j * 306 + k];
    } else if (idx < KEMB * HID + NG * HID) {
        int r = idx - KEMB * HID;
        int g = r >> 9, j = r & (HID - 1);
        g_Wr[r] = W_in[j * 306 + 256 + g];
    } else {
        int r = idx - KEMB * HID - NG * HID;
        int g = r >> 9, j = r & (HID - 1);
        g_Wg[r] = gate_W[j * NG + g];
    }
}

// ================= prep 1: rbf tables (values) =================
__global__ void __launch_bounds__(512, 1) prep_tables() {
    extern __shared__ float smw[];
    float* Ws1 = smw;                 // 50*512
    float* Ws2 = smw + NG * HID;      // 50*512
    float* rbf = smw + 2 * NG * HID;  // 64
    const int tid = threadIdx.x;
    for (int i = tid; i < NG * HID; i += 512) { Ws1[i] = g_Wr[i]; Ws2[i] = g_Wg[i]; }
    __syncthreads();
    const float delta = RBF_R / 49.0f;
    const float coeff = -0.5f / (delta * delta);
    for (int b = blockIdx.x; b <= NB; b += gridDim.x) {
        float d = (float)b * (RBF_R / (float)NB);
        if (tid < NG) { float t = d - (float)tid * delta; rbf[tid] = __expf(coeff * t * t); }
        __syncthreads();
        float a1 = 0.0f, a2 = 0.0f;
#pragma unroll
        for (int g = 0; g < NG; ++g) {
            float r = rbf[g];
            a1 = fmaf(r, Ws1[g * HID + tid], a1);
            a2 = fmaf(r, Ws2[g * HID + tid], a2);
        }
        g_T1v[(size_t)b * HID + tid] = a1;
        g_T2v[(size_t)b * HID + tid] = a2;
        __syncthreads();
    }
}

// ================= prep 2: slopes (bf16) =================
__global__ void prep_slopes() {
    int idx = blockIdx.x * blockDim.x + threadIdx.x;
    if (idx >= NB * HID) return;
    g_T1s[idx] = __float2bfloat16(g_T1v[idx + HID] - g_T1v[idx]);
    g_T2s[idx] = __float2bfloat16(g_T2v[idx + HID] - g_T2v[idx]);
}

// ================= prep 3: P = emb @ W_emb^T + b_in (R1-proven FFMA2 GEMM) =========
#define PP_XSTRIDE 36
__device__ __forceinline__ void fma_block(ull (&acc)[4][4], const float* xr, const float* wr) {
    float4 xv = *(const float4*)xr;
    float4 wa = *(const float4*)wr;
    float4 wb = *(const float4*)(wr + 4);
    ull w0 = pack2(wa.x, wa.y), w1 = pack2(wa.z, wa.w);
    ull w2 = pack2(wb.x, wb.y), w3 = pack2(wb.z, wb.w);
    ull x0 = pack2(xv.x, xv.x), x1 = pack2(xv.y, xv.y);
    ull x2 = pack2(xv.z, xv.z), x3 = pack2(xv.w, xv.w);
    fma2(acc[0][0], w0, x0); fma2(acc[0][1], w1, x0);
    fma2(acc[0][2], w2, x0); fma2(acc[0][3], w3, x0);
    fma2(acc[1][0], w0, x1); fma2(acc[1][1], w1, x1);
    fma2(acc[1][2], w2, x1); fma2(acc[1][3], w3, x1);
    fma2(acc[2][0], w0, x2); fma2(acc[2][1], w1, x2);
    fma2(acc[2][2], w2, x2); fma2(acc[2][3], w3, x2);
    fma2(acc[3][0], w0, x3); fma2(acc[3][1], w1, x3);
    fma2(acc[3][2], w2, x3); fma2(acc[3][3], w3, x3);
}

// smem: Xs 256*36=9216 | WsA 32*512=16384 | WsB 16384 | bs 512  => 42496 f = 169984 B
#define PP_SMEM_BYTES (42496 * 4)
__global__ void __launch_bounds__(512, 1)
prep_P_kernel(const float* __restrict__ emb_table, const float* __restrict__ b_in) {
    extern __shared__ float sm[];
    float* Xs  = sm;
    float* WsA = sm + 9216;
    float* WsB = sm + 9216 + 16384;
    float* bsS = sm + 9216 + 32768;

    const int tid = threadIdx.x;
    const int p0  = blockIdx.x * 32;
    const int eg = tid & 7, jg = tid >> 3, jbase = jg * 8;
    const float4* emb4 = (const float4*)emb_table;

    for (int i = tid; i < 32 * 64; i += 512) {
        int e = i >> 6, c = i & 63;
        int pair = p0 + e;
        float4 v = (pair < NPAIR) ? emb4[(size_t)pair * 64 + c] : make_float4(0, 0, 0, 0);
        int kb = c * 4;
        Xs[(kb + 0) * PP_XSTRIDE + e] = v.x;
        Xs[(kb + 1) * PP_XSTRIDE + e] = v.y;
        Xs[(kb + 2) * PP_XSTRIDE + e] = v.z;
        Xs[(kb + 3) * PP_XSTRIDE + e] = v.w;
    }
    bsS[tid] = b_in[tid];

    {
        uint32_t sbase;
        asm("{ .reg .u64 t; cvta.to.shared.u64 t, %1; cvt.u32.u64 %0, t; }" : "=r"(sbase) : "l"(WsA));
        const float4* src = (const float4*)g_WT;
        for (int i = tid; i < 4096; i += 512) cp16(sbase + i * 16, src + i);
    }
    cp_commit();

    ull acc[4][4];
#pragma unroll
    for (int a = 0; a < 4; a++)
#pragma unroll
        for (int b = 0; b < 4; b++) acc[a][b] = 0ull;

    for (int t = 0; t < 8; ++t) {
        if (t + 1 < 8) {
            float* dstb = ((t + 1) & 1) ? WsB : WsA;
            uint32_t sbase;
            asm("{ .reg .u64 t; cvta.to.shared.u64 t, %1; cvt.u32.u64 %0, t; }" : "=r"(sbase) : "l"(dstb));
            const float4* src = (const float4*)(g_WT + (t + 1) * 32 * HID);
            for (int i = tid; i < 4096; i += 512) cp16(sbase + i * 16, src + i);
        }
        cp_commit();
        cp_wait1();
        __syncthreads();
        const float* W = (t & 1) ? WsB : WsA;
        const int kb = t * 32;
#pragma unroll
        for (int kk = 0; kk < 32; ++kk)
            fma_block(acc, Xs + (kb + kk) * PP_XSTRIDE + eg * 4, W + kk * HID + jbase);
        __syncthreads();
    }

#pragma unroll
    for (int e4 = 0; e4 < 4; ++e4) {
        int pair = p0 + eg * 4 + e4;
        if (pair < NPAIR) {
#pragma unroll
            for (int jp = 0; jp < 4; ++jp) {
                float2 v = unpack2(acc[e4][jp]);
                int j0 = jbase + jp * 2;
                g_P[(size_t)pair * HID + j0]     = v.x + bsS[j0];
                g_P[(size_t)pair * HID + j0 + 1] = v.y + bsS[j0 + 1];
            }
        }
    }
}

// ================= main kernel =================
// 256 threads, 8 warps, 8 edges/warp, 64 edges/CTA.
// smem: Wos[8*512] f32 (16KB) | Rb[8][32*33] (33.8KB) | spidx/sbin/sfrac[64]
#define MT          256
#define BEDG        64
#define WOS_F       (HEADS * HID)              // 4096
#define RB_F        (8 * 32 * 33)              // 8448
#define STG_F       (WOS_F + RB_F)             // 12544
#define MAIN_SMEM_B ((STG_F + 192) * 4)        // 50944 B

__global__ void __launch_bounds__(MT, 2)
pair_main(const int* __restrict__ anum,
          const int* __restrict__ edge_index,
          const int* __restrict__ edge_to_src,
          const float* __restrict__ dist,
          const float* __restrict__ W_out,
          const float* __restrict__ b_out,
          float* __restrict__ out, int E) {
    extern __shared__ float sm[];
    float* Wos   = sm;                  // [h][j] == W_out row-major
    float* Rb    = sm + WOS_F;
    int*   spidx = (int*)(sm + STG_F);
    int*   sbin  = (int*)(sm + STG_F + 64);
    float* sfrac = sm + STG_F + 128;

    const int tid  = threadIdx.x;
    const int wid  = tid >> 5;
    const int lane = tid & 31;
    const int e0   = blockIdx.x * BEDG;

    for (int i = tid; i < WOS_F; i += MT) Wos[i] = W_out[i];
    if (tid < BEDG) {
        int e = e0 + tid; if (e >= E) e = E - 1;
        int f = edge_to_src[e];
        int i0 = edge_index[f];
        int i1 = edge_index[E + f];
        spidx[tid] = anum[i0] + NELEM * anum[i1];
        float x = dist[e] * ((float)NB / RBF_R);
        int b = (int)x; if (b > NB - 1) b = NB - 1;
        sbin[tid] = b;
        sfrac[tid] = x - (float)b;
    }
    __syncthreads();

    const float4* P4  = (const float4*)g_P;
    const float4* T14 = (const float4*)g_T1v;
    const float4* T24 = (const float4*)g_T2v;
    const uint2*  S12 = (const uint2*)g_T1s;
    const uint2*  S22 = (const uint2*)g_T2s;

    float* RbW = Rb + wid * (32 * 33);
    float bo8 = __ldg(&b_out[lane & 7]);

#pragma unroll 1
    for (int grp = 0; grp < 2; ++grp) {
        int pe[4], be[4]; float fe[4];
#pragma unroll
        for (int e4 = 0; e4 < 4; ++e4) {
            int sl = wid * 8 + grp * 4 + e4;
            pe[4 - 4 + e4] = spidx[sl]; be[e4] = sbin[sl]; fe[e4] = sfrac[sl];
        }
        float po[4][8];
#pragma unroll
        for (int a = 0; a < 4; a++)
#pragma unroll
            for (int h = 0; h < 8; h++) po[a][h] = 0.0f;

#pragma unroll
        for (int jq = 0; jq < 4; ++jq) {
            float4 w[8];
#pragma unroll
            for (int h = 0; h < 8; ++h)
                w[h] = *(const float4*)&Wos[h * HID + jq * 128 + lane * 4];
            const int off = jq * 32 + lane;   // float4 / uint2 index within a 512-row
#pragma unroll
            for (int e4 = 0; e4 < 4; ++e4) {
                size_t pr = (size_t)pe[e4] * 128 + off;
                size_t tr = (size_t)be[e4] * 128 + off;
                float  f  = fe[e4];
                float4 pv = __ldg(P4 + pr);
                float4 v1 = __ldg(T14 + tr);
                float4 v2 = __ldg(T24 + tr);
                uint2  s1u = __ldg(S12 + tr);
                uint2  s2u = __ldg(S22 + tr);
                float2 s1a = __bfloat1622float2(*(const __nv_bfloat162*)&s1u.x);
                float2 s1b = __bfloat1622float2(*(const __nv_bfloat162*)&s1u.y);
                float2 s2a = __bfloat1622float2(*(const __nv_bfloat162*)&s2u.x);
                float2 s2b = __bfloat1622float2(*(const __nv_bfloat162*)&s2u.y);
                float4 p, g;
                p.x = pv.x + fmaf(f, s1a.x, v1.x);
                p.y = pv.y + fmaf(f, s1a.y, v1.y);
                p.z = pv.z + fmaf(f, s1b.x, v1.z);
                p.w = pv.w + fmaf(f, s1b.y, v1.w);
                g.x = fmaf(f, s2a.x, v2.x);
                g.y = fmaf(f, s2a.y, v2.y);
                g.z = fmaf(f, s2b.x, v2.z);
                g.w = fmaf(f, s2b.y, v2.w);
                float4 hv;
                hv.x = __fdividef(p.x * g.x, 1.0f + __expf(-p.x));
                hv.y = __fdividef(p.y * g.y, 1.0f + __expf(-p.y));
                hv.z = __fdividef(p.z * g.z, 1.0f + __expf(-p.z));
                hv.w = __fdividef(p.w * g.w, 1.0f + __expf(-p.w));
#pragma unroll
                for (int h = 0; h < 8; ++h) {
                    po[e4][h] = fmaf(hv.x, w[h].x, po[e4][h]);
                    po[e4][h] = fmaf(hv.y, w[h].y, po[e4][h]);
                    po[e4][h] = fmaf(hv.z, w[h].z, po[e4][h]);
                    po[e4][h] = fmaf(hv.w, w[h].w, po[e4][h]);
                }
            }
        }

        // per-warp smem reduction over 32 lanes (conflict-free, deterministic)
#pragma unroll
        for (int e4 = 0; e4 < 4; ++e4)
#pragma unroll
            for (int h = 0; h < 8; ++h)
                RbW[lane * 33 + e4 * 8 + h] = po[e4][h];
        __syncwarp();
        float s = bo8;
#pragma unroll
        for (int l = 0; l < 32; ++l) s += RbW[l * 33 + lane];
        int e4 = lane >> 3, h = lane & 7;
        int ge = e0 + wid * 8 + grp * 4 + e4;
        if (ge < E) out[(size_t)h * E + ge] = s;
        __syncwarp();
    }
}

// ================= launch =================
extern "C" void kernel_launch(void* const* d_in, const int* in_sizes, int n_in,
                              void* d_out, int out_size) {
    const int*   anum        = (const int*)d_in[0];
    const int*   edge_index  = (const int*)d_in[1];
    const int*   edge_to_src = (const int*)d_in[2];
    const float* dist        = (const float*)d_in[3];
    // d_in[4] = emb_table
    const float* emb_table   = (const float*)d_in[4];
    const float* gate_W      = (const float*)d_in[5];
    const float* W_in        = (const float*)d_in[6];
    const float* b_in        = (const float*)d_in[7];
    const float* W_out       = (const float*)d_in[8];
    const float* b_out       = (const float*)d_in[9];
    float* out = (float*)d_out;
    const int E = in_sizes[2];

    // prep 0: weight transposes
    {
        int tot = KEMB * HID + NG * HID * 2;
        prep_transpose<<<(tot + 255) / 256, 256>>>(W_in, gate_W);
    }
    // prep 1: table values
    {
        static const int smem = 2 * NG * HID * 4 + 256;   // 205056 B
        cudaFuncSetAttribute(prep_tables, cudaFuncAttributeMaxDynamicSharedMemorySize, smem);
        prep_tables<<<148, 512, smem>>>();
    }
    // prep 2: slopes
    prep_slopes<<<(NB * HID + 255) / 256, 256>>>();
    // prep 3: pair table P
    cudaFuncSetAttribute(prep_P_kernel, cudaFuncAttributeMaxDynamicSharedMemorySize, PP_SMEM_BYTES);
    prep_P_kernel<<<(NPAIR + 31) / 32, 512, PP_SMEM_BYTES>>>(emb_table, b_in);
    // main
    cudaFuncSetAttribute(pair_main, cudaFuncAttributeMaxDynamicSharedMemorySize, MAIN_SMEM_B);
    pair_main<<<(E + BEDG - 1) / BEDG, MT, MAIN_SMEM_B>>>(
        anum, edge_index, edge_to_src, dist, W_out, b_out, out, E);
}

// round 4
// speedup vs baseline: 8.5985x; 1.1350x over previous
#include <cuda_runtime.h>
#include <cuda_bf16.h>
#include <cuda_fp16.h>
#include <cstdint>

#define NB        4096
#define HID       512
#define KEMB      256
#define NG        50
#define NELEM     100
#define NPAIR     (NELEM * NELEM)       // 10000
#define HEADS     8
#define RBF_R     12.0f

// ---------------- device scratch ----------------
__device__ __align__(16) __half         g_PH[(size_t)NPAIR * HID];     // fp16 (emb@W^T + b_in)
__device__ __align__(16) float          g_T1v[(size_t)(NB + 1) * HID]; // fp32 staging
__device__ __align__(16) float          g_T2v[(size_t)(NB + 1) * HID];
__device__ __align__(16) uint4          g_TP[(size_t)NB * 256];        // packed {v1h x4, v2h x4, s1bf x4, s2bf x4}
__device__ __align__(16) float          g_WT[KEMB * HID];              // W_in emb part, [k][j]
__device__ __align__(16) float          g_Wr[NG * HID];                // W_in rbf part, [g][j]
__device__ __align__(16) float          g_Wg[NG * HID];                // gate_W,       [g][j]

typedef unsigned long long ull;

__device__ __forceinline__ void fma2(ull& d, ull a, ull b) {
    asm("fma.rn.f32x2 %0, %1, %2, %0;" : "+l"(d) : "l"(a), "l"(b));
}
__device__ __forceinline__ ull pack2(float x, float y) {
    ull r; asm("mov.b64 %0, {%1, %2};" : "=l"(r) : "f"(x), "f"(y)); return r;
}
__device__ __forceinline__ float2 unpack2(ull v) {
    float2 r; asm("mov.b64 {%0, %1}, %2;" : "=f"(r.x), "=f"(r.y) : "l"(v)); return r;
}
__device__ __forceinline__ void cp16(uint32_t sa, const void* g) {
    asm volatile("cp.async.cg.shared.global [%0], [%1], 16;" :: "r"(sa), "l"(g));
}
__device__ __forceinline__ void cp_commit() { asm volatile("cp.async.commit_group;"); }
__device__ __forceinline__ void cp_wait1()  { asm volatile("cp.async.wait_group 1;"); }

// ================= prep 0: transposes =================
__global__ void prep_transpose(const float* __restrict__ W_in,
                               const float* __restrict__ gate_W) {
    int idx = blockIdx.x * blockDim.x + threadIdx.x;
    int total = KEMB * HID + NG * HID * 2;
    if (idx >= total) return;
    if (idx < KEMB * HID) {
        int k = idx >> 9, j = idx & (HID - 1);
        g_WT[idx] = W_in[j * 306 + k];
    } else if (idx < KEMB * HID + NG * HID) {
        int r = idx - KEMB * HID;
        int g = r >> 9, j = r & (HID - 1);
        g_Wr[r] = W_in[j * 306 + 256 + g];
    } else {
        int r = idx - KEMB * HID - NG * HID;
        int g = r >> 9, j = r & (HID - 1);
        g_Wg[r] = gate_W[j * NG + g];
    }
}

// ================= prep 1: rbf tables (fp32 values) =================
__global__ void __launch_bounds__(512, 1) prep_tables() {
    extern __shared__ float smw[];
    float* Ws1 = smw;                 // 50*512
    float* Ws2 = smw + NG * HID;      // 50*512
    float* rbf = smw + 2 * NG * HID;  // 64
    const int tid = threadIdx.x;
    for (int i = tid; i < NG * HID; i += 512) { Ws1[i] = g_Wr[i]; Ws2[i] = g_Wg[i]; }
    __syncthreads();
    const float delta = RBF_R / 49.0f;
    const float coeff = -0.5f / (delta * delta);
    for (int b = blockIdx.x; b <= NB; b += gridDim.x) {
        float d = (float)b * (RBF_R / (float)NB);
        if (tid < NG) { float t = d - (float)tid * delta; rbf[tid] = __expf(coeff * t * t); }
        __syncthreads();
        float a1 = 0.0f, a2 = 0.0f;
#pragma unroll
        for (int g = 0; g < NG; ++g) {
            float r = rbf[g];
            a1 = fmaf(r, Ws1[g * HID + tid], a1);
            a2 = fmaf(r, Ws2[g * HID + tid], a2);
        }
        g_T1v[(size_t)b * HID + tid] = a1;
        g_T2v[(size_t)b * HID + tid] = a2;
        __syncthreads();
    }
}

// ================= prep 2: pack fp16 values + bf16 slopes =================
__global__ void prep_pack() {
    int idx = blockIdx.x * blockDim.x + threadIdx.x;   // NB*128 groups
    if (idx >= NB * 128) return;
    int b = idx >> 7, gi = idx & 127;
    const float* v1  = g_T1v + (size_t)b * HID + gi * 4;
    const float* v2  = g_T2v + (size_t)b * HID + gi * 4;
    const float* v1n = v1 + HID;
    const float* v2n = v2 + HID;
    uint4 A, B;
    __half2 h;
    h = __floats2half2_rn(v1[0], v1[1]);  A.x = *(uint32_t*)&h;
    h = __floats2half2_rn(v1[2], v1[3]);  A.y = *(uint32_t*)&h;
    h = __floats2half2_rn(v2[0], v2[1]);  A.z = *(uint32_t*)&h;
    h = __floats2half2_rn(v2[2], v2[3]);  A.w = *(uint32_t*)&h;
    __nv_bfloat162 s;
    s = __floats2bfloat162_rn(v1n[0] - v1[0], v1n[1] - v1[1]); B.x = *(uint32_t*)&s;
    s = __floats2bfloat162_rn(v1n[2] - v1[2], v1n[3] - v1[3]); B.y = *(uint32_t*)&s;
    s = __floats2bfloat162_rn(v2n[0] - v2[0], v2n[1] - v2[1]); B.z = *(uint32_t*)&s;
    s = __floats2bfloat162_rn(v2n[2] - v2[2], v2n[3] - v2[3]); B.w = *(uint32_t*)&s;
    g_TP[(size_t)idx * 2]     = A;
    g_TP[(size_t)idx * 2 + 1] = B;
}

// ================= prep 3: P = emb @ W_emb^T + b_in (FFMA2 GEMM) =========
#define PP_XSTRIDE 36
__device__ __forceinline__ void fma_block(ull (&acc)[4][4], const float* xr, const float* wr) {
    float4 xv = *(const float4*)xr;
    float4 wa = *(const float4*)wr;
    float4 wb = *(const float4*)(wr + 4);
    ull w0 = pack2(wa.x, wa.y), w1 = pack2(wa.z, wa.w);
    ull w2 = pack2(wb.x, wb.y), w3 = pack2(wb.z, wb.w);
    ull x0 = pack2(xv.x, xv.x), x1 = pack2(xv.y, xv.y);
    ull x2 = pack2(xv.z, xv.z), x3 = pack2(xv.w, xv.w);
    fma2(acc[0][0], w0, x0); fma2(acc[0][1], w1, x0);
    fma2(acc[0][2], w2, x0); fma2(acc[0][3], w3, x0);
    fma2(acc[1][0], w0, x1); fma2(acc[1][1], w1, x1);
    fma2(acc[1][2], w2, x1); fma2(acc[1][3], w3, x1);
    fma2(acc[2][0], w0, x2); fma2(acc[2][1], w1, x2);
    fma2(acc[2][2], w2, x2); fma2(acc[2][3], w3, x2);
    fma2(acc[3][0], w0, x3); fma2(acc[3][1], w1, x3);
    fma2(acc[3][2], w2, x3); fma2(acc[3][3], w3, x3);
}

// smem: Xs 256*36=9216 | WsA 16384 | WsB 16384 | bs 512 => 42496 f = 169984 B
#define PP_SMEM_BYTES (42496 * 4)
__global__ void __launch_bounds__(512, 1)
prep_P_kernel(const float* __restrict__ emb_table, const float* __restrict__ b_in) {
    extern __shared__ float sm[];
    float* Xs  = sm;
    float* WsA = sm + 9216;
    float* WsB = sm + 9216 + 16384;
    float* bsS = sm + 9216 + 32768;

    const int tid = threadIdx.x;
    const int p0  = blockIdx.x * 32;
    const int eg = tid & 7, jg = tid >> 3, jbase = jg * 8;
    const float4* emb4 = (const float4*)emb_table;

    for (int i = tid; i < 32 * 64; i += 512) {
        int e = i >> 6, c = i & 63;
        int pair = p0 + e;
        float4 v = (pair < NPAIR) ? emb4[(size_t)pair * 64 + c] : make_float4(0, 0, 0, 0);
        int kb = c * 4;
        Xs[(kb + 0) * PP_XSTRIDE + e] = v.x;
        Xs[(kb + 1) * PP_XSTRIDE + e] = v.y;
        Xs[(kb + 2) * PP_XSTRIDE + e] = v.z;
        Xs[(kb + 3) * PP_XSTRIDE + e] = v.w;
    }
    bsS[tid] = b_in[tid];

    {
        uint32_t sbase;
        asm("{ .reg .u64 t; cvta.to.shared.u64 t, %1; cvt.u32.u64 %0, t; }" : "=r"(sbase) : "l"(WsA));
        const float4* src = (const float4*)g_WT;
        for (int i = tid; i < 4096; i += 512) cp16(sbase + i * 16, src + i);
    }
    cp_commit();

    ull acc[4][4];
#pragma unroll
    for (int a = 0; a < 4; a++)
#pragma unroll
        for (int b = 0; b < 4; b++) acc[a][b] = 0ull;

    for (int t = 0; t < 8; ++t) {
        if (t + 1 < 8) {
            float* dstb = ((t + 1) & 1) ? WsB : WsA;
            uint32_t sbase;
            asm("{ .reg .u64 t; cvta.to.shared.u64 t, %1; cvt.u32.u64 %0, t; }" : "=r"(sbase) : "l"(dstb));
            const float4* src = (const float4*)(g_WT + (t + 1) * 32 * HID);
            for (int i = tid; i < 4096; i += 512) cp16(sbase + i * 16, src + i);
        }
        cp_commit();
        cp_wait1();
        __syncthreads();
        const float* W = (t & 1) ? WsB : WsA;
        const int kb = t * 32;
#pragma unroll
        for (int kk = 0; kk < 32; ++kk)
            fma_block(acc, Xs + (kb + kk) * PP_XSTRIDE + eg * 4, W + kk * HID + jbase);
        __syncthreads();
    }

#pragma unroll
    for (int e4 = 0; e4 < 4; ++e4) {
        int pair = p0 + eg * 4 + e4;
        if (pair < NPAIR) {
#pragma unroll
            for (int jp = 0; jp < 4; ++jp) {
                float2 v = unpack2(acc[e4][jp]);
                int j0 = jbase + jp * 2;
                g_PH[(size_t)pair * HID + j0]     = __float2half(v.x + bsS[j0]);
                g_PH[(size_t)pair * HID + j0 + 1] = __float2half(v.y + bsS[j0 + 1]);
            }
        }
    }
}

// ================= main kernel =================
#define MT          256
#define BEDG        64
#define WOS_F       (HEADS * HID)              // 4096
#define RB_F        (8 * 32 * 33)              // 8448
#define STG_F       (WOS_F + RB_F)             // 12544
#define MAIN_SMEM_B ((STG_F + 192) * 4)        // 50944 B

__global__ void __launch_bounds__(MT, 2)
pair_main(const int* __restrict__ anum,
          const int* __restrict__ edge_index,
          const int* __restrict__ edge_to_src,
          const float* __restrict__ dist,
          const float* __restrict__ W_out,
          const float* __restrict__ b_out,
          float* __restrict__ out, int E) {
    extern __shared__ float sm[];
    float* Wos   = sm;                  // [h][j]
    float* Rb    = sm + WOS_F;
    int*   spidx = (int*)(sm + STG_F);
    int*   sbin  = (int*)(sm + STG_F + 64);
    float* sfrac = sm + STG_F + 128;

    const int tid  = threadIdx.x;
    const int wid  = tid >> 5;
    const int lane = tid & 31;
    const int e0   = blockIdx.x * BEDG;

    for (int i = tid; i < WOS_F; i += MT) Wos[i] = W_out[i];
    if (tid < BEDG) {
        int e = e0 + tid; if (e >= E) e = E - 1;
        int f = edge_to_src[e];
        int i0 = edge_index[f];
        int i1 = edge_index[E + f];
        spidx[tid] = anum[i0] + NELEM * anum[i1];
        float x = dist[e] * ((float)NB / RBF_R);
        int b = (int)x; if (b > NB - 1) b = NB - 1;
        sbin[tid] = b;
        sfrac[tid] = x - (float)b;
    }
    __syncthreads();

    const uint2* P2 = (const uint2*)g_PH;
    float* RbW = Rb + wid * (32 * 33);
    float bo8 = __ldg(&b_out[lane & 7]);

#pragma unroll 1
    for (int grp = 0; grp < 2; ++grp) {
        int pe[4], be[4]; float fe[4];
#pragma unroll
        for (int e4 = 0; e4 < 4; ++e4) {
            int sl = wid * 8 + grp * 4 + e4;
            pe[e4] = spidx[sl]; be[e4] = sbin[sl]; fe[e4] = sfrac[sl];
        }
        float po[4][8];
#pragma unroll
        for (int a = 0; a < 4; a++)
#pragma unroll
            for (int h = 0; h < 8; h++) po[a][h] = 0.0f;

#pragma unroll
        for (int jq = 0; jq < 4; ++jq) {
            float4 w[8];
#pragma unroll
            for (int h = 0; h < 8; ++h)
                w[h] = *(const float4*)&Wos[h * HID + jq * 128 + lane * 4];
            const int off = jq * 32 + lane;   // 4-hidden group index within 128
#pragma unroll
            for (int e4 = 0; e4 < 4; ++e4) {
                size_t tr = (size_t)be[e4] * 256 + (size_t)off * 2;
                uint4 tA = __ldg(g_TP + tr);
                uint4 tB = __ldg(g_TP + tr + 1);
                uint2 ph = __ldg(P2 + (size_t)pe[e4] * 128 + off);
                float f  = fe[e4];
                float2 P01 = __half22float2(*(const __half2*)&ph.x);
                float2 P23 = __half22float2(*(const __half2*)&ph.y);
                float2 V1a = __half22float2(*(const __half2*)&tA.x);
                float2 V1b = __half22float2(*(const __half2*)&tA.y);
                float2 V2a = __half22float2(*(const __half2*)&tA.z);
                float2 V2b = __half22float2(*(const __half2*)&tA.w);
                float2 S1a = __bfloat1622float2(*(const __nv_bfloat162*)&tB.x);
                float2 S1b = __bfloat1622float2(*(const __nv_bfloat162*)&tB.y);
                float2 S2a = __bfloat1622float2(*(const __nv_bfloat162*)&tB.z);
                float2 S2b = __bfloat1622float2(*(const __nv_bfloat162*)&tB.w);
                float4 p, g;
                p.x = fmaf(f, S1a.x, P01.x + V1a.x);
                p.y = fmaf(f, S1a.y, P01.y + V1a.y);
                p.z = fmaf(f, S1b.x, P23.x + V1b.x);
                p.w = fmaf(f, S1b.y, P23.y + V1b.y);
                g.x = fmaf(f, S2a.x, V2a.x);
                g.y = fmaf(f, S2a.y, V2a.y);
                g.z = fmaf(f, S2b.x, V2b.x);
                g.w = fmaf(f, S2b.y, V2b.y);
                float4 hv;
                hv.x = __fdividef(p.x * g.x, 1.0f + __expf(-p.x));
                hv.y = __fdividef(p.y * g.y, 1.0f + __expf(-p.y));
                hv.z = __fdividef(p.z * g.z, 1.0f + __expf(-p.z));
                hv.w = __fdividef(p.w * g.w, 1.0f + __expf(-p.w));
#pragma unroll
                for (int h = 0; h < 8; ++h) {
                    po[e4][h] = fmaf(hv.x, w[h].x, po[e4][h]);
                    po[e4][h] = fmaf(hv.y, w[h].y, po[e4][h]);
                    po[e4][h] = fmaf(hv.z, w[h].z, po[e4][h]);
                    po[e4][h] = fmaf(hv.w, w[h].w, po[e4][h]);
                }
            }
        }

        // per-warp smem reduction (conflict-free, deterministic)
#pragma unroll
        for (int e4 = 0; e4 < 4; ++e4)
#pragma unroll
            for (int h = 0; h < 8; ++h)
                RbW[lane * 33 + e4 * 8 + h] = po[e4][h];
        __syncwarp();
        float s = bo8;
#pragma unroll
        for (int l = 0; l < 32; ++l) s += RbW[l * 33 + lane];
        int e4 = lane >> 3, h = lane & 7;
        int ge = e0 + wid * 8 + grp * 4 + e4;
        if (ge < E) out[(size_t)h * E + ge] = s;
        __syncwarp();
    }
}

// ================= launch =================
extern "C" void kernel_launch(void* const* d_in, const int* in_sizes, int n_in,
                              void* d_out, int out_size) {
    const int*   anum        = (const int*)d_in[0];
    const int*   edge_index  = (const int*)d_in[1];
    const int*   edge_to_src = (const int*)d_in[2];
    const float* dist        = (const float*)d_in[3];
    const float* emb_table   = (const float*)d_in[4];
    const float* gate_W      = (const float*)d_in[5];
    const float* W_in        = (const float*)d_in[6];
    const float* b_in        = (const float*)d_in[7];
    const float* W_out       = (const float*)d_in[8];
    const float* b_out       = (const float*)d_in[9];
    float* out = (float*)d_out;
    const int E = in_sizes[2];

    {
        int tot = KEMB * HID + NG * HID * 2;
        prep_transpose<<<(tot + 255) / 256, 256>>>(W_in, gate_W);
    }
    {
        static const int smem = 2 * NG * HID * 4 + 256;
        cudaFuncSetAttribute(prep_tables, cudaFuncAttributeMaxDynamicSharedMemorySize, smem);
        prep_tables<<<148, 512, smem>>>();
    }
    prep_pack<<<(NB * 128 + 255) / 256, 256>>>();
    cudaFuncSetAttribute(prep_P_kernel, cudaFuncAttributeMaxDynamicSharedMemorySize, PP_SMEM_BYTES);
    prep_P_kernel<<<(NPAIR + 31) / 32, 512, PP_SMEM_BYTES>>>(emb_table, b_in);
    cudaFuncSetAttribute(pair_main, cudaFuncAttributeMaxDynamicSharedMemorySize, MAIN_SMEM_B);
    pair_main<<<(E + BEDG - 1) / BEDG, MT, MAIN_SMEM_B>>>(
        anum, edge_index, edge_to_src, dist, W_out, b_out, out, E);
}

// round 5
// speedup vs baseline: 8.9574x; 1.0417x over previous
#include <cuda_runtime.h>
#include <cuda_bf16.h>
#include <cuda_fp16.h>
#include <cstdint>

#define NB        4096
#define HID       512
#define KEMB      256
#define NG        50
#define NELEM     100
#define NPAIR     (NELEM * NELEM)       // 10000
#define HEADS     8
#define RBF_R     12.0f

// ---------------- device scratch ----------------
__device__ __align__(16) __half         g_PH[(size_t)NPAIR * HID];     // fp16 (emb@W^T + b_in)
__device__ __align__(16) uint4          g_TP[(size_t)NB * 256];        // packed {v1h x4, v2h x4, s1bf x4, s2bf x4}
__device__ __align__(16) float          g_WT[KEMB * HID];              // W_in emb part, [k][j]
__device__ __align__(16) float          g_Wr[NG * HID];                // W_in rbf part, [g][j]
__device__ __align__(16) float          g_Wg[NG * HID];                // gate_W,       [g][j]

typedef unsigned long long ull;

__device__ __forceinline__ void fma2(ull& d, ull a, ull b) {
    asm("fma.rn.f32x2 %0, %1, %2, %0;" : "+l"(d) : "l"(a), "l"(b));
}
__device__ __forceinline__ ull pack2(float x, float y) {
    ull r; asm("mov.b64 %0, {%1, %2};" : "=l"(r) : "f"(x), "f"(y)); return r;
}
__device__ __forceinline__ float2 unpack2(ull v) {
    float2 r; asm("mov.b64 {%0, %1}, %2;" : "=f"(r.x), "=f"(r.y) : "l"(v)); return r;
}
__device__ __forceinline__ float rcpa(float x) {
    float r; asm("rcp.approx.ftz.f32 %0, %1;" : "=f"(r) : "f"(x)); return r;
}
__device__ __forceinline__ void cp16(uint32_t sa, const void* g) {
    asm volatile("cp.async.cg.shared.global [%0], [%1], 16;" :: "r"(sa), "l"(g));
}
__device__ __forceinline__ void cp_commit() { asm volatile("cp.async.commit_group;"); }
__device__ __forceinline__ void cp_wait1()  { asm volatile("cp.async.wait_group 1;"); }

// ================= prep 0: transposes =================
__global__ void prep_transpose(const float* __restrict__ W_in,
                               const float* __restrict__ gate_W) {
    int idx = blockIdx.x * blockDim.x + threadIdx.x;
    int total = KEMB * HID + NG * HID * 2;
    if (idx >= total) return;
    if (idx < KEMB * HID) {
        int k = idx >> 9, j = idx & (HID - 1);
        g_WT[idx] = W_in[j * 306 + k];
    } else if (idx < KEMB * HID + NG * HID) {
        int r = idx - KEMB * HID;
        int g = r >> 9, j = r & (HID - 1);
        g_Wr[r] = W_in[j * 306 + 256 + g];
    } else {
        int r = idx - KEMB * HID - NG * HID;
        int g = r >> 9, j = r & (HID - 1);
        g_Wg[r] = gate_W[j * NG + g];
    }
}

// ================= prep 1: rbf tables, packed directly =================
// smem: Ws1 50*512 | Ws2 50*512 | sv 4*512 | rbf 64 | rbfn 64
#define TBL_SMEM ((2 * NG * HID + 4 * HID + 128) * 4)
__global__ void __launch_bounds__(512, 1) prep_tables_pack() {
    extern __shared__ float smw[];
    float* Ws1  = smw;
    float* Ws2  = smw + NG * HID;
    float* sv1  = smw + 2 * NG * HID;        // [512]
    float* sv2  = sv1 + HID;
    float* sv1n = sv2 + HID;
    float* sv2n = sv1n + HID;
    float* rbf  = sv2n + HID;                // [64]
    float* rbfn = rbf + 64;                  // [64]
    const int tid = threadIdx.x;
    for (int i = tid; i < NG * HID; i += 512) { Ws1[i] = g_Wr[i]; Ws2[i] = g_Wg[i]; }
    __syncthreads();
    const float delta = RBF_R / 49.0f;
    const float coeff = -0.5f / (delta * delta);
    const float binw  = RBF_R / (float)NB;
    for (int b = blockIdx.x; b < NB; b += gridDim.x) {
        if (tid < NG) {
            float t = (float)b * binw - (float)tid * delta;
            rbf[tid] = __expf(coeff * t * t);
        } else if (tid >= 64 && tid < 64 + NG) {
            float t = (float)(b + 1) * binw - (float)(tid - 64) * delta;
            rbfn[tid - 64] = __expf(coeff * t * t);
        }
        __syncthreads();
        float a1 = 0.f, a2 = 0.f, a1n = 0.f, a2n = 0.f;
#pragma unroll
        for (int g = 0; g < NG; ++g) {
            float r = rbf[g], rn = rbfn[g];
            float w1 = Ws1[g * HID + tid], w2 = Ws2[g * HID + tid];
            a1  = fmaf(r,  w1, a1);   a2  = fmaf(r,  w2, a2);
            a1n = fmaf(rn, w1, a1n);  a2n = fmaf(rn, w2, a2n);
        }
        sv1[tid] = a1; sv2[tid] = a2; sv1n[tid] = a1n; sv2n[tid] = a2n;
        __syncthreads();
        if (tid < 128) {
            int q = tid * 4;
            uint4 A, B;
            __half2 h;
            h = __floats2half2_rn(sv1[q],     sv1[q + 1]); A.x = *(uint32_t*)&h;
            h = __floats2half2_rn(sv1[q + 2], sv1[q + 3]); A.y = *(uint32_t*)&h;
            h = __floats2half2_rn(sv2[q],     sv2[q + 1]); A.z = *(uint32_t*)&h;
            h = __floats2half2_rn(sv2[q + 2], sv2[q + 3]); A.w = *(uint32_t*)&h;
            __nv_bfloat162 s;
            s = __floats2bfloat162_rn(sv1n[q]     - sv1[q],     sv1n[q + 1] - sv1[q + 1]); B.x = *(uint32_t*)&s;
            s = __floats2bfloat162_rn(sv1n[q + 2] - sv1[q + 2], sv1n[q + 3] - sv1[q + 3]); B.y = *(uint32_t*)&s;
            s = __floats2bfloat162_rn(sv2n[q]     - sv2[q],     sv2n[q + 1] - sv2[q + 1]); B.z = *(uint32_t*)&s;
            s = __floats2bfloat162_rn(sv2n[q + 2] - sv2[q + 2], sv2n[q + 3] - sv2[q + 3]); B.w = *(uint32_t*)&s;
            size_t o = ((size_t)b * 128 + tid) * 2;
            g_TP[o]     = A;
            g_TP[o + 1] = B;
        }
        __syncthreads();
    }
}

// ================= prep 2: P = emb @ W_emb^T + b_in (FFMA2 GEMM) =========
#define PP_XSTRIDE 36
__device__ __forceinline__ void fma_block(ull (&acc)[4][4], const float* xr, const float* wr) {
    float4 xv = *(const float4*)xr;
    const ull* wp = (const ull*)wr;          // f32 pair in consecutive regs == f32x2 operand
    ull w0 = wp[0], w1 = wp[1], w2 = wp[2], w3 = wp[3];
    ull x0 = pack2(xv.x, xv.x), x1 = pack2(xv.y, xv.y);
    ull x2 = pack2(xv.z, xv.z), x3 = pack2(xv.w, xv.w);
    fma2(acc[0][0], w0, x0); fma2(acc[0][1], w1, x0);
    fma2(acc[0][2], w2, x0); fma2(acc[0][3], w3, x0);
    fma2(acc[1][0], w0, x1); fma2(acc[1][1], w1, x1);
    fma2(acc[1][2], w2, x1); fma2(acc[1][3], w3, x1);
    fma2(acc[2][0], w0, x2); fma2(acc[2][1], w1, x2);
    fma2(acc[2][2], w2, x2); fma2(acc[2][3], w3, x2);
    fma2(acc[3][0], w0, x3); fma2(acc[3][1], w1, x3);
    fma2(acc[3][2], w2, x3); fma2(acc[3][3], w3, x3);
}

// smem: Xs 256*36=9216 | WsA 16384 | WsB 16384 | bs 512 => 42496 f = 169984 B
#define PP_SMEM_BYTES (42496 * 4)
__global__ void __launch_bounds__(512, 1)
prep_P_kernel(const float* __restrict__ emb_table, const float* __restrict__ b_in) {
    extern __shared__ float sm[];
    float* Xs  = sm;
    float* WsA = sm + 9216;
    float* WsB = sm + 9216 + 16384;
    float* bsS = sm + 9216 + 32768;

    const int tid = threadIdx.x;
    const int p0  = blockIdx.x * 32;
    const int eg = tid & 7, jg = tid >> 3, jbase = jg * 8;
    const float4* emb4 = (const float4*)emb_table;

    for (int i = tid; i < 32 * 64; i += 512) {
        int e = i >> 6, c = i & 63;
        int pair = p0 + e;
        float4 v = (pair < NPAIR) ? emb4[(size_t)pair * 64 + c] : make_float4(0, 0, 0, 0);
        int kb = c * 4;
        Xs[(kb + 0) * PP_XSTRIDE + e] = v.x;
        Xs[(kb + 1) * PP_XSTRIDE + e] = v.y;
        Xs[(kb + 2) * PP_XSTRIDE + e] = v.z;
        Xs[(kb + 3) * PP_XSTRIDE + e] = v.w;
    }
    bsS[tid] = b_in[tid];

    {
        uint32_t sbase;
        asm("{ .reg .u64 t; cvta.to.shared.u64 t, %1; cvt.u32.u64 %0, t; }" : "=r"(sbase) : "l"(WsA));
        const float4* src = (const float4*)g_WT;
        for (int i = tid; i < 4096; i += 512) cp16(sbase + i * 16, src + i);
    }
    cp_commit();

    ull acc[4][4];
#pragma unroll
    for (int a = 0; a < 4; a++)
#pragma unroll
        for (int b = 0; b < 4; b++) acc[a][b] = 0ull;

    for (int t = 0; t < 8; ++t) {
        if (t + 1 < 8) {
            float* dstb = ((t + 1) & 1) ? WsB : WsA;
            uint32_t sbase;
            asm("{ .reg .u64 t; cvta.to.shared.u64 t, %1; cvt.u32.u64 %0, t; }" : "=r"(sbase) : "l"(dstb));
            const float4* src = (const float4*)(g_WT + (t + 1) * 32 * HID);
            for (int i = tid; i < 4096; i += 512) cp16(sbase + i * 16, src + i);
        }
        cp_commit();
        cp_wait1();
        __syncthreads();
        const float* W = (t & 1) ? WsB : WsA;
        const int kb = t * 32;
#pragma unroll
        for (int kk = 0; kk < 32; ++kk)
            fma_block(acc, Xs + (kb + kk) * PP_XSTRIDE + eg * 4, W + kk * HID + jbase);
        __syncthreads();
    }

#pragma unroll
    for (int e4 = 0; e4 < 4; ++e4) {
        int pair = p0 + eg * 4 + e4;
        if (pair < NPAIR) {
#pragma unroll
            for (int jp = 0; jp < 4; ++jp) {
                float2 v = unpack2(acc[e4][jp]);
                int j0 = jbase + jp * 2;
                g_PH[(size_t)pair * HID + j0]     = __float2half(v.x + bsS[j0]);
                g_PH[(size_t)pair * HID + j0 + 1] = __float2half(v.y + bsS[j0 + 1]);
            }
        }
    }
}

// ================= main kernel =================
#define MT          256
#define BEDG        64
#define WOS_F       (HEADS * HID)              // 4096
#define RB_F        (8 * 32 * 33)              // 8448
#define STG_F       (WOS_F + RB_F)             // 12544
#define MAIN_SMEM_B ((STG_F + 192) * 4)        // 50944 B

__global__ void __launch_bounds__(MT, 2)
pair_main(const int* __restrict__ anum,
          const int* __restrict__ edge_index,
          const int* __restrict__ edge_to_src,
          const float* __restrict__ dist,
          const float* __restrict__ W_out,
          const float* __restrict__ b_out,
          float* __restrict__ out, int E) {
    extern __shared__ float sm[];
    float* Wos   = sm;                  // [h][j]
    float* Rb    = sm + WOS_F;
    int*   spidx = (int*)(sm + STG_F);
    int*   sbin  = (int*)(sm + STG_F + 64);
    float* sfrac = sm + STG_F + 128;

    const int tid  = threadIdx.x;
    const int wid  = tid >> 5;
    const int lane = tid & 31;
    const int e0   = blockIdx.x * BEDG;

    for (int i = tid; i < WOS_F; i += MT) Wos[i] = W_out[i];
    if (tid < BEDG) {
        int e = e0 + tid; if (e >= E) e = E - 1;
        int f = edge_to_src[e];
        int i0 = edge_index[f];
        int i1 = edge_index[E + f];
        spidx[tid] = anum[i0] + NELEM * anum[i1];
        float x = dist[e] * ((float)NB / RBF_R);
        int b = (int)x; if (b > NB - 1) b = NB - 1;
        sbin[tid] = b;
        sfrac[tid] = x - (float)b;
    }
    __syncthreads();

    const uint2* P2 = (const uint2*)g_PH;
    float* RbW = Rb + wid * (32 * 33);
    float bo8 = __ldg(&b_out[lane & 7]);

#pragma unroll 1
    for (int grp = 0; grp < 2; ++grp) {
        int pe[4], be[4]; float fe[4];
#pragma unroll
        for (int e4 = 0; e4 < 4; ++e4) {
            int sl = wid * 8 + grp * 4 + e4;
            pe[e4] = spidx[sl]; be[e4] = sbin[sl]; fe[e4] = sfrac[sl];
        }
        float po[4][8];
#pragma unroll
        for (int a = 0; a < 4; a++)
#pragma unroll
            for (int h = 0; h < 8; h++) po[a][h] = 0.0f;

#pragma unroll
        for (int jq = 0; jq < 4; ++jq) {
            float4 w[8];
#pragma unroll
            for (int h = 0; h < 8; ++h)
                w[h] = *(const float4*)&Wos[h * HID + jq * 128 + lane * 4];
            const int off = jq * 32 + lane;   // 4-hidden group index within 128
#pragma unroll
            for (int e4 = 0; e4 < 4; ++e4) {
                size_t tr = (size_t)be[e4] * 256 + (size_t)off * 2;
                uint4 tA = __ldg(g_TP + tr);
                uint4 tB = __ldg(g_TP + tr + 1);
                uint2 ph = __ldg(P2 + (size_t)pe[e4] * 128 + off);
                float f  = fe[e4];
                float2 P01 = __half22float2(*(const __half2*)&ph.x);
                float2 P23 = __half22float2(*(const __half2*)&ph.y);
                float2 V1a = __half22float2(*(const __half2*)&tA.x);
                float2 V1b = __half22float2(*(const __half2*)&tA.y);
                float2 V2a = __half22float2(*(const __half2*)&tA.z);
                float2 V2b = __half22float2(*(const __half2*)&tA.w);
                float2 S1a = __bfloat1622float2(*(const __nv_bfloat162*)&tB.x);
                float2 S1b = __bfloat1622float2(*(const __nv_bfloat162*)&tB.y);
                float2 S2a = __bfloat1622float2(*(const __nv_bfloat162*)&tB.z);
                float2 S2b = __bfloat1622float2(*(const __nv_bfloat162*)&tB.w);
                float4 p, g;
                p.x = fmaf(f, S1a.x, P01.x + V1a.x);
                p.y = fmaf(f, S1a.y, P01.y + V1a.y);
                p.z = fmaf(f, S1b.x, P23.x + V1b.x);
                p.w = fmaf(f, S1b.y, P23.y + V1b.y);
                g.x = fmaf(f, S2a.x, V2a.x);
                g.y = fmaf(f, S2a.y, V2a.y);
                g.z = fmaf(f, S2b.x, V2b.x);
                g.w = fmaf(f, S2b.y, V2b.y);
                // silu(p)*g with batched reciprocal: 4 ex2 + 1 rcp per 4 hiddens
                float q0 = 1.0f + __expf(-p.x);
                float q1 = 1.0f + __expf(-p.y);
                float q2 = 1.0f + __expf(-p.z);
                float q3 = 1.0f + __expf(-p.w);
                float q01 = q0 * q1, q23 = q2 * q3;
                float rall = rcpa(q01 * q23);
                float r01 = rall * q23, r23 = rall * q01;
                float4 hv;
                hv.x = p.x * g.x * (r01 * q1);
                hv.y = p.y * g.y * (r01 * q0);
                hv.z = p.z * g.z * (r23 * q3);
                hv.w = p.w * g.w * (r23 * q2);
#pragma unroll
                for (int h = 0; h < 8; ++h) {
                    po[e4][h] = fmaf(hv.x, w[h].x, po[e4][h]);
                    po[e4][h] = fmaf(hv.y, w[h].y, po[e4][h]);
                    po[e4][h] = fmaf(hv.z, w[h].z, po[e4][h]);
                    po[e4][h] = fmaf(hv.w, w[h].w, po[e4][h]);
                }
            }
        }

        // per-warp smem reduction (conflict-free, deterministic)
#pragma unroll
        for (int e4 = 0; e4 < 4; ++e4)
#pragma unroll
            for (int h = 0; h < 8; ++h)
                RbW[lane * 33 + e4 * 8 + h] = po[e4][h];
        __syncwarp();
        float s = bo8;
#pragma unroll
        for (int l = 0; l < 32; ++l) s += RbW[l * 33 + lane];
        int e4 = lane >> 3, h = lane & 7;
        int ge = e0 + wid * 8 + grp * 4 + e4;
        if (ge < E) out[(size_t)h * E + ge] = s;
        __syncwarp();
    }
}

// ================= launch =================
extern "C" void kernel_launch(void* const* d_in, const int* in_sizes, int n_in,
                              void* d_out, int out_size) {
    const int*   anum        = (const int*)d_in[0];
    const int*   edge_index  = (const int*)d_in[1];
    const int*   edge_to_src = (const int*)d_in[2];
    const float* dist        = (const float*)d_in[3];
    const float* emb_table   = (const float*)d_in[4];
    const float* gate_W      = (const float*)d_in[5];
    const float* W_in        = (const float*)d_in[6];
    const float* b_in        = (const float*)d_in[7];
    const float* W_out       = (const float*)d_in[8];
    const float* b_out       = (const float*)d_in[9];
    float* out = (float*)d_out;
    const int E = in_sizes[2];

    {
        int tot = KEMB * HID + NG * HID * 2;
        prep_transpose<<<(tot + 255) / 256, 256>>>(W_in, gate_W);
    }
    cudaFuncSetAttribute(prep_tables_pack, cudaFuncAttributeMaxDynamicSharedMemorySize, TBL_SMEM);
    prep_tables_pack<<<148, 512, TBL_SMEM>>>();
    cudaFuncSetAttribute(prep_P_kernel, cudaFuncAttributeMaxDynamicSharedMemorySize, PP_SMEM_BYTES);
    prep_P_kernel<<<(NPAIR + 31) / 32, 512, PP_SMEM_BYTES>>>(emb_table, b_in);
    cudaFuncSetAttribute(pair_main, cudaFuncAttributeMaxDynamicSharedMemorySize, MAIN_SMEM_B);
    pair_main<<<(E + BEDG - 1) / BEDG, MT, MAIN_SMEM_B>>>(
        anum, edge_index, edge_to_src, dist, W_out, b_out, out, E);
}

// round 6
// speedup vs baseline: 8.9991x; 1.0047x over previous
#include <cuda_runtime.h>
#include <cuda_bf16.h>
#include <cuda_fp16.h>
#include <cstdint>

#define NB        4096
#define HID       512
#define KEMB      256
#define NG        50
#define NELEM     100
#define NPAIR     (NELEM * NELEM)       // 10000
#define HEADS     8
#define RBF_R     12.0f

// ---------------- device scratch ----------------
__device__ __align__(16) __half         g_PH[(size_t)NPAIR * HID];     // fp16 (emb@W^T + b_in)
__device__ __align__(16) uint4          g_TPa[(size_t)NB * 128];       // values {v1h x4, v2h x4}
__device__ __align__(16) uint4          g_TPb[(size_t)NB * 128];       // slopes {s1h x4, s2h x4} (fp16)
__device__ __align__(16) float          g_WT[KEMB * HID];              // W_in emb part, [k][j]
__device__ __align__(16) float          g_Wr[NG * HID];                // W_in rbf part, [g][j]
__device__ __align__(16) float          g_Wg[NG * HID];                // gate_W,       [g][j]

typedef unsigned long long ull;

__device__ __forceinline__ void fma2(ull& d, ull a, ull b) {
    asm("fma.rn.f32x2 %0, %1, %2, %0;" : "+l"(d) : "l"(a), "l"(b));
}
__device__ __forceinline__ ull pack2(float x, float y) {
    ull r; asm("mov.b64 %0, {%1, %2};" : "=l"(r) : "f"(x), "f"(y)); return r;
}
__device__ __forceinline__ float2 unpack2(ull v) {
    float2 r; asm("mov.b64 {%0, %1}, %2;" : "=f"(r.x), "=f"(r.y) : "l"(v)); return r;
}
__device__ __forceinline__ float rcpa(float x) {
    float r; asm("rcp.approx.ftz.f32 %0, %1;" : "=f"(r) : "f"(x)); return r;
}
__device__ __forceinline__ void cp16(uint32_t sa, const void* g) {
    asm volatile("cp.async.cg.shared.global [%0], [%1], 16;" :: "r"(sa), "l"(g));
}
__device__ __forceinline__ void cp_commit() { asm volatile("cp.async.commit_group;"); }
__device__ __forceinline__ void cp_wait1()  { asm volatile("cp.async.wait_group 1;"); }

// ================= prep 0: transposes =================
__global__ void prep_transpose(const float* __restrict__ W_in,
                               const float* __restrict__ gate_W) {
    int idx = blockIdx.x * blockDim.x + threadIdx.x;
    int total = KEMB * HID + NG * HID * 2;
    if (idx >= total) return;
    if (idx < KEMB * HID) {
        int k = idx >> 9, j = idx & (HID - 1);
        g_WT[idx] = W_in[j * 306 + k];
    } else if (idx < KEMB * HID + NG * HID) {
        int r = idx - KEMB * HID;
        int g = r >> 9, j = r & (HID - 1);
        g_Wr[r] = W_in[j * 306 + 256 + g];
    } else {
        int r = idx - KEMB * HID - NG * HID;
        int g = r >> 9, j = r & (HID - 1);
        g_Wg[r] = gate_W[j * NG + g];
    }
}

// ================= prep 1: rbf tables, packed SoA =================
// smem: Ws1 50*512 | Ws2 50*512 | sv 4*512 | rbf 64 | rbfn 64
#define TBL_SMEM ((2 * NG * HID + 4 * HID + 128) * 4)
__global__ void __launch_bounds__(512, 1) prep_tables_pack() {
    extern __shared__ float smw[];
    float* Ws1  = smw;
    float* Ws2  = smw + NG * HID;
    float* sv1  = smw + 2 * NG * HID;        // [512]
    float* sv2  = sv1 + HID;
    float* sv1n = sv2 + HID;
    float* sv2n = sv1n + HID;
    float* rbf  = sv2n + HID;                // [64]
    float* rbfn = rbf + 64;                  // [64]
    const int tid = threadIdx.x;
    for (int i = tid; i < NG * HID; i += 512) { Ws1[i] = g_Wr[i]; Ws2[i] = g_Wg[i]; }
    __syncthreads();
    const float delta = RBF_R / 49.0f;
    const float coeff = -0.5f / (delta * delta);
    const float binw  = RBF_R / (float)NB;
    for (int b = blockIdx.x; b < NB; b += gridDim.x) {
        if (tid < NG) {
            float t = (float)b * binw - (float)tid * delta;
            rbf[tid] = __expf(coeff * t * t);
        } else if (tid >= 64 && tid < 64 + NG) {
            float t = (float)(b + 1) * binw - (float)(tid - 64) * delta;
            rbfn[tid - 64] = __expf(coeff * t * t);
        }
        __syncthreads();
        float a1 = 0.f, a2 = 0.f, a1n = 0.f, a2n = 0.f;
#pragma unroll
        for (int g = 0; g < NG; ++g) {
            float r = rbf[g], rn = rbfn[g];
            float w1 = Ws1[g * HID + tid], w2 = Ws2[g * HID + tid];
            a1  = fmaf(r,  w1, a1);   a2  = fmaf(r,  w2, a2);
            a1n = fmaf(rn, w1, a1n);  a2n = fmaf(rn, w2, a2n);
        }
        sv1[tid] = a1; sv2[tid] = a2; sv1n[tid] = a1n; sv2n[tid] = a2n;
        __syncthreads();
        if (tid < 128) {
            int q = tid * 4;
            uint4 A, B;
            __half2 h;
            h = __floats2half2_rn(sv1[q],     sv1[q + 1]); A.x = *(uint32_t*)&h;
            h = __floats2half2_rn(sv1[q + 2], sv1[q + 3]); A.y = *(uint32_t*)&h;
            h = __floats2half2_rn(sv2[q],     sv2[q + 1]); A.z = *(uint32_t*)&h;
            h = __floats2half2_rn(sv2[q + 2], sv2[q + 3]); A.w = *(uint32_t*)&h;
            h = __floats2half2_rn(sv1n[q]     - sv1[q],     sv1n[q + 1] - sv1[q + 1]); B.x = *(uint32_t*)&h;
            h = __floats2half2_rn(sv1n[q + 2] - sv1[q + 2], sv1n[q + 3] - sv1[q + 3]); B.y = *(uint32_t*)&h;
            h = __floats2half2_rn(sv2n[q]     - sv2[q],     sv2n[q + 1] - sv2[q + 1]); B.z = *(uint32_t*)&h;
            h = __floats2half2_rn(sv2n[q + 2] - sv2[q + 2], sv2n[q + 3] - sv2[q + 3]); B.w = *(uint32_t*)&h;
            size_t o = (size_t)b * 128 + tid;
            g_TPa[o] = A;
            g_TPb[o] = B;
        }
        __syncthreads();
    }
}

// ================= prep 2: P = emb @ W_emb^T + b_in (FFMA2 GEMM) =========
#define PP_XSTRIDE 36
__device__ __forceinline__ void fma_block(ull (&acc)[4][4], const float* xr, const float* wr) {
    float4 xv = *(const float4*)xr;
    const ull* wp = (const ull*)wr;          // f32 pair in consecutive regs == f32x2 operand
    ull w0 = wp[0], w1 = wp[1], w2 = wp[2], w3 = wp[3];
    ull x0 = pack2(xv.x, xv.x), x1 = pack2(xv.y, xv.y);
    ull x2 = pack2(xv.z, xv.z), x3 = pack2(xv.w, xv.w);
    fma2(acc[0][0], w0, x0); fma2(acc[0][1], w1, x0);
    fma2(acc[0][2], w2, x0); fma2(acc[0][3], w3, x0);
    fma2(acc[1][0], w0, x1); fma2(acc[1][1], w1, x1);
    fma2(acc[1][2], w2, x1); fma2(acc[1][3], w3, x1);
    fma2(acc[2][0], w0, x2); fma2(acc[2][1], w1, x2);
    fma2(acc[2][2], w2, x2); fma2(acc[2][3], w3, x2);
    fma2(acc[3][0], w0, x3); fma2(acc[3][1], w1, x3);
    fma2(acc[3][2], w2, x3); fma2(acc[3][3], w3, x3);
}

// smem: Xs 256*36=9216 | WsA 16384 | WsB 16384 | bs 512 => 42496 f = 169984 B
#define PP_SMEM_BYTES (42496 * 4)
__global__ void __launch_bounds__(512, 1)
prep_P_kernel(const float* __restrict__ emb_table, const float* __restrict__ b_in) {
    extern __shared__ float sm[];
    float* Xs  = sm;
    float* WsA = sm + 9216;
    float* WsB = sm + 9216 + 16384;
    float* bsS = sm + 9216 + 32768;

    const int tid = threadIdx.x;
    const int p0  = blockIdx.x * 32;
    const int eg = tid & 7, jg = tid >> 3, jbase = jg * 8;
    const float4* emb4 = (const float4*)emb_table;

    for (int i = tid; i < 32 * 64; i += 512) {
        int e = i >> 6, c = i & 63;
        int pair = p0 + e;
        float4 v = (pair < NPAIR) ? emb4[(size_t)pair * 64 + c] : make_float4(0, 0, 0, 0);
        int kb = c * 4;
        Xs[(kb + 0) * PP_XSTRIDE + e] = v.x;
        Xs[(kb + 1) * PP_XSTRIDE + e] = v.y;
        Xs[(kb + 2) * PP_XSTRIDE + e] = v.z;
        Xs[(kb + 3) * PP_XSTRIDE + e] = v.w;
    }
    bsS[tid] = b_in[tid];

    {
        uint32_t sbase;
        asm("{ .reg .u64 t; cvta.to.shared.u64 t, %1; cvt.u32.u64 %0, t; }" : "=r"(sbase) : "l"(WsA));
        const float4* src = (const float4*)g_WT;
        for (int i = tid; i < 4096; i += 512) cp16(sbase + i * 16, src + i);
    }
    cp_commit();

    ull acc[4][4];
#pragma unroll
    for (int a = 0; a < 4; a++)
#pragma unroll
        for (int b = 0; b < 4; b++) acc[a][b] = 0ull;

    for (int t = 0; t < 8; ++t) {
        if (t + 1 < 8) {
            float* dstb = ((t + 1) & 1) ? WsB : WsA;
            uint32_t sbase;
            asm("{ .reg .u64 t; cvta.to.shared.u64 t, %1; cvt.u32.u64 %0, t; }" : "=r"(sbase) : "l"(dstb));
            const float4* src = (const float4*)(g_WT + (t + 1) * 32 * HID);
            for (int i = tid; i < 4096; i += 512) cp16(sbase + i * 16, src + i);
        }
        cp_commit();
        cp_wait1();
        __syncthreads();
        const float* W = (t & 1) ? WsB : WsA;
        const int kb = t * 32;
#pragma unroll
        for (int kk = 0; kk < 32; ++kk)
            fma_block(acc, Xs + (kb + kk) * PP_XSTRIDE + eg * 4, W + kk * HID + jbase);
        __syncthreads();
    }

#pragma unroll
    for (int e4 = 0; e4 < 4; ++e4) {
        int pair = p0 + eg * 4 + e4;
        if (pair < NPAIR) {
#pragma unroll
            for (int jp = 0; jp < 4; ++jp) {
                float2 v = unpack2(acc[e4][jp]);
                int j0 = jbase + jp * 2;
                g_PH[(size_t)pair * HID + j0]     = __float2half(v.x + bsS[j0]);
                g_PH[(size_t)pair * HID + j0 + 1] = __float2half(v.y + bsS[j0 + 1]);
            }
        }
    }
}

// ================= main kernel =================
#define MT          256
#define BEDG        64
#define WOS_F       (HEADS * HID)              // 4096
#define RB_F        (8 * 32 * 33)              // 8448
#define STG_F       (WOS_F + RB_F)             // 12544
#define MAIN_SMEM_B ((STG_F + 192) * 4)        // 50944 B

__global__ void __launch_bounds__(MT, 2)
pair_main(const int* __restrict__ anum,
          const int* __restrict__ edge_index,
          const int* __restrict__ edge_to_src,
          const float* __restrict__ dist,
          const float* __restrict__ W_out,
          const float* __restrict__ b_out,
          float* __restrict__ out, int E) {
    extern __shared__ float sm[];
    float* Wos   = sm;                  // [h][j]
    float* Rb    = sm + WOS_F;
    int*   spidx = (int*)(sm + STG_F);
    int*   sbin  = (int*)(sm + STG_F + 64);
    float* sfrac = sm + STG_F + 128;

    const int tid  = threadIdx.x;
    const int wid  = tid >> 5;
    const int lane = tid & 31;
    const int e0   = blockIdx.x * BEDG;

    for (int i = tid; i < WOS_F; i += MT) Wos[i] = W_out[i];
    if (tid < BEDG) {
        int e = e0 + tid; if (e >= E) e = E - 1;
        int f = edge_to_src[e];
        int i0 = edge_index[f];
        int i1 = edge_index[E + f];
        spidx[tid] = anum[i0] + NELEM * anum[i1];
        float x = dist[e] * ((float)NB / RBF_R);
        int b = (int)x; if (b > NB - 1) b = NB - 1;
        sbin[tid] = b;
        sfrac[tid] = x - (float)b;
    }
    __syncthreads();

    const uint2* P2 = (const uint2*)g_PH;
    float* RbW = Rb + wid * (32 * 33);
    float bo8 = __ldg(&b_out[lane & 7]);

#pragma unroll 1
    for (int grp = 0; grp < 2; ++grp) {
        int pe[4], be[4]; __half2 fh2[4];
#pragma unroll
        for (int e4 = 0; e4 < 4; ++e4) {
            int sl = wid * 8 + grp * 4 + e4;
            pe[e4] = spidx[sl]; be[e4] = sbin[sl];
            fh2[e4] = __float2half2_rn(sfrac[sl]);
        }
        ull po2[4][4];                 // [edge][head-pair] f32x2 accumulators
#pragma unroll
        for (int a = 0; a < 4; a++)
#pragma unroll
            for (int b = 0; b < 4; b++) po2[a][b] = 0ull;

#pragma unroll
        for (int jq = 0; jq < 4; ++jq) {
            const int off = jq * 32 + lane;   // 4-hidden group index within 128
            // pack head-pair weights: wp[hp][jpos] = (w[2hp][jpos], w[2hp+1][jpos])
            ull wp[4][4];
#pragma unroll
            for (int hp = 0; hp < 4; ++hp) {
                float4 wa = *(const float4*)&Wos[(2 * hp)     * HID + jq * 128 + lane * 4];
                float4 wb = *(const float4*)&Wos[(2 * hp + 1) * HID + jq * 128 + lane * 4];
                wp[hp][0] = pack2(wa.x, wb.x);
                wp[hp][1] = pack2(wa.y, wb.y);
                wp[hp][2] = pack2(wa.z, wb.z);
                wp[hp][3] = pack2(wa.w, wb.w);
            }
#pragma unroll
            for (int e4 = 0; e4 < 4; ++e4) {
                size_t tr = (size_t)be[e4] * 128 + off;
                uint4 tA = __ldg(g_TPa + tr);
                uint4 tB = __ldg(g_TPb + tr);
                uint2 ph = __ldg(P2 + (size_t)pe[e4] * 128 + off);
                __half2 f2 = fh2[e4];
                // fp16 lerp: t = v + f*s ; p = P + t
                __half2 t1a = __hfma2(f2, *(const __half2*)&tB.x, *(const __half2*)&tA.x);
                __half2 t1b = __hfma2(f2, *(const __half2*)&tB.y, *(const __half2*)&tA.y);
                __half2 g2a = __hfma2(f2, *(const __half2*)&tB.z, *(const __half2*)&tA.z);
                __half2 g2b = __hfma2(f2, *(const __half2*)&tB.w, *(const __half2*)&tA.w);
                __half2 pa  = __hadd2(*(const __half2*)&ph.x, t1a);
                __half2 pb  = __hadd2(*(const __half2*)&ph.y, t1b);
                float2 p01 = __half22float2(pa);
                float2 p23 = __half22float2(pb);
                float2 g01 = __half22float2(g2a);
                float2 g23 = __half22float2(g2b);
                // silu(p)*g with batched reciprocal: 4 ex2 + 1 rcp
                float q0 = 1.0f + __expf(-p01.x);
                float q1 = 1.0f + __expf(-p01.y);
                float q2 = 1.0f + __expf(-p23.x);
                float q3 = 1.0f + __expf(-p23.y);
                float q01 = q0 * q1, q23 = q2 * q3;
                float rall = rcpa(q01 * q23);
                float r01 = rall * q23, r23 = rall * q01;
                float hv0 = p01.x * g01.x * (r01 * q1);
                float hv1 = p01.y * g01.y * (r01 * q0);
                float hv2 = p23.x * g23.x * (r23 * q3);
                float hv3 = p23.y * g23.y * (r23 * q2);
                ull h0 = pack2(hv0, hv0), h1 = pack2(hv1, hv1);
                ull h2 = pack2(hv2, hv2), h3 = pack2(hv3, hv3);
#pragma unroll
                for (int hp = 0; hp < 4; ++hp) {
                    fma2(po2[e4][hp], wp[hp][0], h0);
                    fma2(po2[e4][hp], wp[hp][1], h1);
                    fma2(po2[e4][hp], wp[hp][2], h2);
                    fma2(po2[e4][hp], wp[hp][3], h3);
                }
            }
        }

        // per-warp smem reduction (conflict-free, deterministic)
#pragma unroll
        for (int e4 = 0; e4 < 4; ++e4)
#pragma unroll
            for (int hp = 0; hp < 4; ++hp) {
                float2 v = unpack2(po2[e4][hp]);
                RbW[lane * 33 + e4 * 8 + 2 * hp]     = v.x;
                RbW[lane * 33 + e4 * 8 + 2 * hp + 1] = v.y;
            }
        __syncwarp();
        float s = bo8;
#pragma unroll
        for (int l = 0; l < 32; ++l) s += RbW[l * 33 + lane];
        int e4 = lane >> 3, h = lane & 7;
        int ge = e0 + wid * 8 + grp * 4 + e4;
        if (ge < E) out[(size_t)h * E + ge] = s;
        __syncwarp();
    }
}

// ================= launch =================
extern "C" void kernel_launch(void* const* d_in, const int* in_sizes, int n_in,
                              void* d_out, int out_size) {
    const int*   anum        = (const int*)d_in[0];
    const int*   edge_index  = (const int*)d_in[1];
    const int*   edge_to_src = (const int*)d_in[2];
    const float* dist        = (const float*)d_in[3];
    const float* emb_table   = (const float*)d_in[4];
    const float* gate_W      = (const float*)d_in[5];
    const float* W_in        = (const float*)d_in[6];
    const float* b_in        = (const float*)d_in[7];
    const float* W_out       = (const float*)d_in[8];
    const float* b_out       = (const float*)d_in[9];
    float* out = (float*)d_out;
    const int E = in_sizes[2];

    {
        int tot = KEMB * HID + NG * HID * 2;
        prep_transpose<<<(tot + 255) / 256, 256>>>(W_in, gate_W);
    }
    cudaFuncSetAttribute(prep_tables_pack, cudaFuncAttributeMaxDynamicSharedMemorySize, TBL_SMEM);
    prep_tables_pack<<<148, 512, TBL_SMEM>>>();
    cudaFuncSetAttribute(prep_P_kernel, cudaFuncAttributeMaxDynamicSharedMemorySize, PP_SMEM_BYTES);
    prep_P_kernel<<<(NPAIR + 31) / 32, 512, PP_SMEM_BYTES>>>(emb_table, b_in);
    cudaFuncSetAttribute(pair_main, cudaFuncAttributeMaxDynamicSharedMemorySize, MAIN_SMEM_B);
    pair_main<<<(E + BEDG - 1) / BEDG, MT, MAIN_SMEM_B>>>(
        anum, edge_index, edge_to_src, dist, W_out, b_out, out, E);
}